// round 11
// baseline (speedup 1.0000x reference)
#include <cuda_runtime.h>
#include <cstdint>

// ChannelExchangeWithConv: N=1, C=128, H=W=512, p=2
// R10 base + 2D warp tiling (4 px-groups x 2 o-groups) to halve GEMM LDS traffic.

#define HW    262144
#define TP    128
#define CH    64
#define WROW  68
#define NT    (HW / TP)       // 2048 tiles per direction
#define NJOBS (2 * NT)        // 4096
#define NCTAS 296             // 2 per SM

typedef unsigned long long u64;

__device__ __forceinline__ u64 pkdup(float x) {
    u64 r; asm("mov.b64 %0, {%1, %1};" : "=l"(r) : "f"(x)); return r;
}
__device__ __forceinline__ u64 pk2(float x, float y) {
    u64 r; asm("mov.b64 %0, {%1, %2};" : "=l"(r) : "f"(x), "f"(y)); return r;
}
__device__ __forceinline__ void unpk(u64 v, float& lo, float& hi) {
    asm("mov.b64 {%0, %1}, %2;" : "=f"(lo), "=f"(hi) : "l"(v));
}
#define FMA2(acc, a, b) \
    asm("fma.rn.f32x2 %0, %1, %2, %0;" : "+l"(acc) : "l"(a), "l"(b))

__device__ __forceinline__ void cpasync16(uint32_t s, const void* g) {
    asm volatile("cp.async.cg.shared.global [%0], [%1], 16;" :: "r"(s), "l"(g));
}

__global__ __launch_bounds__(256, 2)
void cx_kernel(const float* __restrict__ lst, const float* __restrict__ gui,
               const float* __restrict__ w1,  const float* __restrict__ b1,
               const float* __restrict__ w2,  const float* __restrict__ b2,
               float* __restrict__ out)
{
    extern __shared__ float smem[];
    float* Xbuf = smem;                         // [2][64][128] double-buffered x tiles
    float* Wt   = smem + 2 * CH * TP;           // [2][64][68]
    float* Bs   = Wt + 2 * CH * WROW;           // [2][64]

    const int tid = threadIdx.x;
    const int bx  = blockIdx.x;

    // --- stage BOTH weight sets (transposed) + biases, once per CTA ---
    #pragma unroll
    for (int i = 0; i < 32; i++) {
        int idx = i * 256 + tid;
        int d   = idx >> 12;
        int o   = (idx >> 6) & 63;
        int c   = idx & 63;
        const float* W = d ? w1 : w2;
        Wt[(d * CH + c) * WROW + o] = W[o * CH + c];
    }
    if (tid < 2 * CH) Bs[tid] = (tid < CH) ? b2[tid] : b1[tid - CH];

    // x-tile cp.async mapping: [64 rows][32 float4 cols]
    const int lrow = tid >> 5;
    const int lcol = (tid & 31) << 2;
    // copy mapping
    const int crow = tid >> 5;
    const int ccol = (tid & 31) << 2;

    const uint32_t sX0 = (uint32_t)__cvta_generic_to_shared(Xbuf);
    const uint32_t sX1 = (uint32_t)__cvta_generic_to_shared(Xbuf + CH * TP);

    // GEMM mapping: 8 warps = 4 px-groups x 2 o-groups (warp tile 32px x 32o)
    // lane = 8 px-subgroups (4px) x 4 o-subgroups (8o); thread tile 4px x 8o
    const int warp = tid >> 5;
    const int q    = tid & 31;
    const int P    = warp >> 1;            // 0..3
    const int O    = warp & 1;             // 0..1
    const int px    = P * 32 + (q & 7) * 4;     // thread's 4 pixels
    const int obase = O * 32 + (q >> 3) * 8;    // thread's 8 conv outputs

    // --- prologue: prefetch job0 x-tile into buf0 ---
    {
        int j = bx;
        int dir = j >> 11, tile = j & (NT - 1);
        const float* xin = dir ? lst : gui;
        const float* gp  = xin + (size_t)tile * TP + lcol;
        #pragma unroll
        for (int i = 0; i < 8; i++) {
            cpasync16(sX0 + (uint32_t)((lrow + 8 * i) * TP + lcol) * 4,
                      gp + (size_t)(2 * (lrow + 8 * i)) * HW);
        }
        asm volatile("cp.async.commit_group;");
    }

    int it = 0;
    for (int j = bx; j < NJOBS; j += NCTAS, it++) {
        const int cur = it & 1;
        const int dir = j >> 11, tile = j & (NT - 1);
        const int pix0 = tile * TP;
        const float* cpin = dir ? gui : lst;
        float* oo = out + (size_t)dir * 128 * HW;

        asm volatile("cp.async.wait_group 0;");
        __syncthreads();

        const float* Xs = Xbuf + cur * CH * TP;
        const float* Wd = Wt + dir * CH * WROW + obase;
        const float* Bd = Bs + dir * CH;

        // next-tile prefetch params (issued spread over blocks 0..3)
        const int jn = j + NCTAS;
        const bool havenext = (jn < NJOBS);
        const int dn = jn >> 11, tn = jn & (NT - 1);
        const float* gpN = (dn ? lst : gui) + (size_t)tn * TP + lcol;
        const uint32_t sdst = cur ? sX0 : sX1;

        // acc init with bias
        u64 acc[4][4];
        #pragma unroll
        for (int jj = 0; jj < 4; jj++) {
            u64 bb = pk2(Bd[obase + 2 * jj], Bd[obase + 2 * jj + 1]);
            acc[0][jj] = bb; acc[1][jj] = bb; acc[2][jj] = bb; acc[3][jj] = bb;
        }

        const float* xp = Xs + px;
        const float* cbase = cpin + pix0 + ccol;
        float*       obuf  = oo + pix0 + ccol;

        // copy pipeline preload: chunks 0,1
        float4 cpv[8];
        cpv[0] = *(const float4*)(cbase + (size_t)(2 * (0 * 8 + crow) + 1) * HW);
        cpv[1] = *(const float4*)(cbase + (size_t)(2 * (1 * 8 + crow) + 1) * HW);

        // --- k-loop: 8 blocks x 8 k, copy + prefetch threaded through ---
        #pragma unroll
        for (int b = 0; b < 8; b++) {
            if (b < 4 && havenext) {
                cpasync16(sdst + (uint32_t)((lrow + 8 * (2 * b)) * TP + lcol) * 4,
                          gpN + (size_t)(2 * (lrow + 8 * (2 * b))) * HW);
                cpasync16(sdst + (uint32_t)((lrow + 8 * (2 * b + 1)) * TP + lcol) * 4,
                          gpN + (size_t)(2 * (lrow + 8 * (2 * b + 1))) * HW);
            }
            if (b == 3 && havenext)
                asm volatile("cp.async.commit_group;");

            #pragma unroll
            for (int cc = 0; cc < 8; cc++) {
                const int c = b * 8 + cc;
                float4 xv = *(const float4*)(xp + c * TP);
                u64 x0 = pkdup(xv.x), x1 = pkdup(xv.y), x2 = pkdup(xv.z), x3 = pkdup(xv.w);
                const u64* wr = (const u64*)(Wd + c * WROW);
                ulonglong2 wa = *(const ulonglong2*)(wr);
                ulonglong2 wb = *(const ulonglong2*)(wr + 2);
                u64 w[4] = {wa.x, wa.y, wb.x, wb.y};
                #pragma unroll
                for (int jj = 0; jj < 4; jj++) {
                    FMA2(acc[0][jj], w[jj], x0);
                    FMA2(acc[1][jj], w[jj], x1);
                    FMA2(acc[2][jj], w[jj], x2);
                    FMA2(acc[3][jj], w[jj], x3);
                }
            }

            if (b < 6)
                cpv[b + 2] = *(const float4*)(cbase + (size_t)(2 * ((b + 2) * 8 + crow) + 1) * HW);
            *(float4*)(obuf + (size_t)(2 * (b * 8 + crow) + 1) * HW) = cpv[b];
        }

        // GEMM output stores: pair jj = conv o (obase+2jj,+1) -> global ch 2*obase+4jj,+2
        #pragma unroll
        for (int jj = 0; jj < 4; jj++) {
            float a0, a1, b0v, b1v, c0, c1, d0, d1;
            unpk(acc[0][jj], a0, a1);
            unpk(acc[1][jj], b0v, b1v);
            unpk(acc[2][jj], c0, c1);
            unpk(acc[3][jj], d0, d1);
            size_t ch0 = (size_t)2 * obase + 4 * jj;
            *(float4*)(oo + ch0 * HW + pix0 + px)       = make_float4(a0, b0v, c0, d0);
            *(float4*)(oo + (ch0 + 2) * HW + pix0 + px) = make_float4(a1, b1v, c1, d1);
        }
    }
}

extern "C" void kernel_launch(void* const* d_in, const int* in_sizes, int n_in,
                              void* d_out, int out_size)
{
    const float* lst = (const float*)d_in[0];
    const float* gui = (const float*)d_in[1];
    const float* w1  = (const float*)d_in[2];
    const float* b1  = (const float*)d_in[3];
    const float* w2  = (const float*)d_in[4];
    const float* b2  = (const float*)d_in[5];
    float* out = (float*)d_out;

    const size_t smem = (size_t)2 * CH * TP * 4 + (size_t)2 * CH * WROW * 4 + 2 * CH * 4; // 100864 B
    cudaFuncSetAttribute(cx_kernel, cudaFuncAttributeMaxDynamicSharedMemorySize, (int)smem);

    cx_kernel<<<NCTAS, 256, smem>>>(lst, gui, w1, b1, w2, b2, out);
}